// round 16
// baseline (speedup 1.0000x reference)
#include <cuda_runtime.h>
#include <cuda_fp16.h>
#include <cstdint>

// Problem constants
static constexpr int HID  = 1024;
static constexpr int NB   = 4;
static constexpr int SEQ  = 2048;
static constexpr int ROWS = NB * SEQ; // 8192

// ---------------------------------------------------------------------------
// Scratch (device globals; allocation-free rule). Everything fp16 except the
// final output. QKV is one fused [8192, 3072] buffer (Q | K | V columns).
// ---------------------------------------------------------------------------
__device__ __half g_Xh [(size_t)ROWS * HID];
__device__ __half g_Wh [(size_t)3 * HID * HID];   // stacked Wq|Wk|Wv, [3072,1024]
__device__ float  g_b3 [3 * HID];                 // packed bq|bk|bv
__device__ __half g_QKV[(size_t)ROWS * 3 * HID];  // [8192, 3072]
__device__ __half g_Vth[(size_t)ROWS * HID];      // [b][h][s]
__device__ __half g_Sch[(size_t)NB * SEQ * SEQ];  // scores fp16 (pre-softmax)
__device__ __half g_Ph [(size_t)NB * SEQ * SEQ];  // softmax(P) fp16

// ---------------------------------------------------------------------------
// PTX helpers
// ---------------------------------------------------------------------------
__device__ __forceinline__ uint32_t smem_u32(const void* p) {
    uint32_t a;
    asm("{ .reg .u64 t; cvta.to.shared.u64 t, %1; cvt.u32.u64 %0, t; }"
        : "=r"(a) : "l"(p));
    return a;
}
__device__ __forceinline__ void cp_async16(uint32_t dst, const void* src) {
    asm volatile("cp.async.cg.shared.global [%0], [%1], 16;"
                 :: "r"(dst), "l"(src) : "memory");
}
#define CP_COMMIT()  asm volatile("cp.async.commit_group;" ::: "memory")
#define CP_WAIT(n)   asm volatile("cp.async.wait_group %0;" :: "n"(n) : "memory")

__device__ __forceinline__ void ldm_x4(uint32_t& r0, uint32_t& r1,
                                       uint32_t& r2, uint32_t& r3, uint32_t addr) {
    asm volatile("ldmatrix.sync.aligned.m8n8.x4.shared.b16 {%0,%1,%2,%3}, [%4];"
                 : "=r"(r0), "=r"(r1), "=r"(r2), "=r"(r3) : "r"(addr));
}
__device__ __forceinline__ void mma_f16(float& d0, float& d1, float& d2, float& d3,
                                        uint32_t a0, uint32_t a1, uint32_t a2, uint32_t a3,
                                        uint32_t b0, uint32_t b1) {
    asm volatile(
        "mma.sync.aligned.m16n8k16.row.col.f32.f16.f16.f32 "
        "{%0,%1,%2,%3}, {%4,%5,%6,%7}, {%8,%9}, {%0,%1,%2,%3};"
        : "+f"(d0), "+f"(d1), "+f"(d2), "+f"(d3)
        : "r"(a0), "r"(a1), "r"(a2), "r"(a3), "r"(b0), "r"(b1));
}

// ---------------------------------------------------------------------------
// Tile config: BM=128, BN=256, BK=64, 4 stages, 512 threads (16 warps, 4x4).
// Rows padded to 144B: conflict-free ldmatrix. Per stage: A[128x64]+B[256x64].
// ---------------------------------------------------------------------------
static constexpr int RS        = 144;
static constexpr int B_OFF     = 128 * RS;            // 18432
static constexpr int STG_BYTES = B_OFF + 256 * RS;    // 55296
static constexpr int SMEM_BYTES = 4 * STG_BYTES;      // 221184

__device__ __forceinline__ void stage_load(
    const __half* __restrict__ Ah, const __half* __restrict__ Bh,
    int lda, int ldb, int k0, uint32_t sb, int tid)
{
#pragma unroll
    for (int i = 0; i < 2; i++) {
        const int v = tid + (i << 9);
        const int r = v >> 3, c = v & 7;
        cp_async16(sb + (uint32_t)(r * RS + (c << 4)),
                   Ah + (size_t)r * lda + k0 + (c << 3));
    }
#pragma unroll
    for (int i = 0; i < 4; i++) {
        const int v = tid + (i << 9);
        const int r = v >> 3, c = v & 7;
        cp_async16(sb + (uint32_t)(B_OFF + r * RS + (c << 4)),
                   Bh + (size_t)r * ldb + k0 + (c << 3));
    }
}

// ---------------------------------------------------------------------------
// Single-pass fp16 GEMM NT: C = alpha * A·B^T + bias
// A: [M,K] fp16 lead-dim lda; B: [N,K] fp16 lead-dim ldb.
// C!=null -> fp32 out (ldc); Ch!=null -> fp16 out (ldc). blockIdx.z batches.
// ---------------------------------------------------------------------------
__global__ void __launch_bounds__(512, 1)
gemm1_mma_kernel(const __half* __restrict__ Ah, const __half* __restrict__ Bh,
                 const float* __restrict__ bias,
                 float* __restrict__ C, __half* __restrict__ Ch,
                 int K, int lda, int ldb, int ldc, float alpha,
                 size_t sA, size_t sB, size_t sC)
{
    extern __shared__ char smem[];
    const uint32_t sbase = smem_u32(smem);
    const int tid = threadIdx.x;
    const int wid = tid >> 5;
    const int lid = tid & 31;
    const int wm  = wid >> 2;   // 0..3 : 32-row slab
    const int wn  = wid & 3;    // 0..3 : 64-col slab

    Ah += (size_t)blockIdx.z * sA + (size_t)blockIdx.y * 128 * lda;
    Bh += (size_t)blockIdx.z * sB + (size_t)blockIdx.x * 256 * ldb;
    const size_t zC = (size_t)blockIdx.z * sC;

    float acc[2][8][4];
#pragma unroll
    for (int mi = 0; mi < 2; mi++)
#pragma unroll
        for (int ni = 0; ni < 8; ni++)
#pragma unroll
            for (int r = 0; r < 4; r++) acc[mi][ni][r] = 0.0f;

    const int nch = K >> 6;

    stage_load(Ah, Bh, lda, ldb, 0, sbase, tid);
    CP_COMMIT();
    stage_load(Ah, Bh, lda, ldb, 64, sbase + STG_BYTES, tid);
    CP_COMMIT();
    stage_load(Ah, Bh, lda, ldb, 128, sbase + 2 * STG_BYTES, tid);
    CP_COMMIT();

    const int a_row = wm * 32 + (((lid >> 3) & 1) << 3) + (lid & 7); // + mi*16
    const int a_chs = (lid >> 4) & 1;                                // + ks*2
    const int b_row = wn * 64 + (((lid >> 4) & 1) << 3) + (lid & 7); // + pr*16
    const int b_chs = (lid >> 3) & 1;                                // + ks*2

    for (int c = 0; c < nch; c++) {
        CP_WAIT(2);
        __syncthreads();

        if (c + 3 < nch)
            stage_load(Ah, Bh, lda, ldb, (c + 3) << 6,
                       sbase + (uint32_t)(((c + 3) & 3) * STG_BYTES), tid);
        CP_COMMIT();   // always commit: uniform group count keeps CP_WAIT(2) exact

        const uint32_t tb = sbase + (uint32_t)((c & 3) * STG_BYTES);
#pragma unroll
        for (int ks = 0; ks < 4; ks++) {
            uint32_t ah[2][4];
            const uint32_t acol = (uint32_t)(((ks << 1) + a_chs) << 4);
            const uint32_t bcol = (uint32_t)(((ks << 1) + b_chs) << 4);
#pragma unroll
            for (int mi = 0; mi < 2; mi++) {
                const uint32_t ad = tb + (uint32_t)((a_row + mi * 16) * RS) + acol;
                ldm_x4(ah[mi][0], ah[mi][1], ah[mi][2], ah[mi][3], ad);
            }
#pragma unroll
            for (int pr = 0; pr < 4; pr++) {
                uint32_t bh[4];
                const uint32_t bd = tb + (uint32_t)(B_OFF + (b_row + pr * 16) * RS) + bcol;
                ldm_x4(bh[0], bh[1], bh[2], bh[3], bd);
#pragma unroll
                for (int mi = 0; mi < 2; mi++)
#pragma unroll
                    for (int q = 0; q < 2; q++) {
                        const int of = q << 1;
                        float* d = acc[mi][pr * 2 + q];
                        mma_f16(d[0], d[1], d[2], d[3],
                                ah[mi][0], ah[mi][1], ah[mi][2], ah[mi][3],
                                bh[of], bh[of + 1]);
                    }
            }
        }
    }

    // Epilogue
    const int t4 = lid >> 2;
    const int t2 = (lid & 3) << 1;
#pragma unroll
    for (int ni = 0; ni < 8; ni++) {
        const int gcol = blockIdx.x * 256 + wn * 64 + ni * 8 + t2;
        float bi0 = 0.0f, bi1 = 0.0f;
        if (bias) { bi0 = bias[gcol]; bi1 = bias[gcol + 1]; }
#pragma unroll
        for (int mi = 0; mi < 2; mi++) {
            const int grow = blockIdx.y * 128 + wm * 32 + mi * 16 + t4;
            const float* d = acc[mi][ni];
            float v00 = fmaf(alpha, d[0], bi0);
            float v01 = fmaf(alpha, d[1], bi1);
            float v10 = fmaf(alpha, d[2], bi0);
            float v11 = fmaf(alpha, d[3], bi1);
            const size_t o0 = zC + (size_t)grow * ldc + gcol;
            const size_t o1 = o0 + (size_t)8 * ldc;
            if (C) {
                *reinterpret_cast<float2*>(C + o0) = make_float2(v00, v01);
                *reinterpret_cast<float2*>(C + o1) = make_float2(v10, v11);
            }
            if (Ch) {
                *reinterpret_cast<__half2*>(Ch + o0) =
                    __halves2half2(__float2half(v00), __float2half(v01));
                *reinterpret_cast<__half2*>(Ch + o1) =
                    __halves2half2(__float2half(v10), __float2half(v11));
            }
        }
    }
}

// ---------------------------------------------------------------------------
// fp32 -> fp16 convert, vectorized by 4
// ---------------------------------------------------------------------------
__global__ void __launch_bounds__(256)
cvt_kernel(const float* __restrict__ x, __half* __restrict__ hi, int n4)
{
    int i = blockIdx.x * 256 + threadIdx.x;
    if (i >= n4) return;
    float4 v = reinterpret_cast<const float4*>(x)[i];
    reinterpret_cast<__half2*>(hi)[2 * i] =
        __halves2half2(__float2half(v.x), __float2half(v.y));
    reinterpret_cast<__half2*>(hi)[2 * i + 1] =
        __halves2half2(__float2half(v.z), __float2half(v.w));
}

// Pack bq|bk|bv into one 3072 vector
__global__ void pack_bias_kernel(const float* __restrict__ bq,
                                 const float* __restrict__ bk,
                                 const float* __restrict__ bv,
                                 float* __restrict__ b3)
{
    const int tid = threadIdx.x;
    const float* src = (blockIdx.x == 0) ? bq : (blockIdx.x == 1) ? bk : bv;
    b3[blockIdx.x * HID + tid] = src[tid];
}

// ---------------------------------------------------------------------------
// V slice of QKV [8192, 3072] (cols 2048..3071) fp16 -> Vt [b][h][s] fp16
// ---------------------------------------------------------------------------
__global__ void __launch_bounds__(256)
transpose_h_kernel(const __half* __restrict__ QKV, __half* __restrict__ Th)
{
    __shared__ __half tile[32][34];
    const int b = blockIdx.z;
    const int h0 = blockIdx.x * 32, s0 = blockIdx.y * 32;
    const int tx = threadIdx.x & 31, ty = threadIdx.x >> 5; // 32 x 8
    const __half* Vb = QKV + (size_t)b * SEQ * (3 * HID) + 2 * HID;
#pragma unroll
    for (int j = 0; j < 32; j += 8)
        tile[ty + j][tx] = Vb[(size_t)(s0 + ty + j) * (3 * HID) + h0 + tx];
    __syncthreads();
    __half* Thb = Th + (size_t)b * HID * SEQ;
#pragma unroll
    for (int j = 0; j < 32; j += 8)
        Thb[(size_t)(h0 + ty + j) * SEQ + s0 + tx] = tile[tx][ty + j];
}

// ---------------------------------------------------------------------------
// Row softmax (2048 cols), fp16 in -> fp16 out
// ---------------------------------------------------------------------------
__global__ void __launch_bounds__(256)
softmax_h_kernel(const __half* __restrict__ Sc, __half* __restrict__ Ph)
{
    __shared__ float red[256];
    const int tid = threadIdx.x;
    const __half2* row = reinterpret_cast<const __half2*>(Sc + (size_t)blockIdx.x * SEQ);

    __half2 h[4];
#pragma unroll
    for (int j = 0; j < 4; j++) h[j] = row[4 * tid + j];
    float p[8];
#pragma unroll
    for (int j = 0; j < 4; j++) {
        float2 f = __half22float2(h[j]);
        p[2 * j] = f.x; p[2 * j + 1] = f.y;
    }

    float m = p[0];
#pragma unroll
    for (int j = 1; j < 8; j++) m = fmaxf(m, p[j]);
    red[tid] = m;
    __syncthreads();
#pragma unroll
    for (int s = 128; s > 0; s >>= 1) {
        if (tid < s) red[tid] = fmaxf(red[tid], red[tid + s]);
        __syncthreads();
    }
    m = red[0];
    __syncthreads();

    float sum = 0.0f;
#pragma unroll
    for (int j = 0; j < 8; j++) { p[j] = __expf(p[j] - m); sum += p[j]; }
    red[tid] = sum;
    __syncthreads();
#pragma unroll
    for (int s = 128; s > 0; s >>= 1) {
        if (tid < s) red[tid] += red[tid + s];
        __syncthreads();
    }
    const float inv = 1.0f / red[0];

    __half2* H = reinterpret_cast<__half2*>(Ph + (size_t)blockIdx.x * SEQ);
#pragma unroll
    for (int j = 0; j < 4; j++)
        H[4 * tid + j] = __halves2half2(__float2half(p[2 * j] * inv),
                                        __float2half(p[2 * j + 1] * inv));
}

// ---------------------------------------------------------------------------
// Launch
// ---------------------------------------------------------------------------
extern "C" void kernel_launch(void* const* d_in, const int* in_sizes, int n_in,
                              void* d_out, int out_size)
{
    const float* X  = (const float*)d_in[0];
    const float* Wq = (const float*)d_in[1];
    const float* bq = (const float*)d_in[2];
    const float* Wk = (const float*)d_in[3];
    const float* bk = (const float*)d_in[4];
    const float* Wv = (const float*)d_in[5];
    const float* bv = (const float*)d_in[6];
    float* out = (float*)d_out;

    __half *Xh, *Wh, *QKV, *Vth, *Sch, *Ph;
    float *b3;
    cudaGetSymbolAddress((void**)&Xh,  g_Xh);
    cudaGetSymbolAddress((void**)&Wh,  g_Wh);
    cudaGetSymbolAddress((void**)&b3,  g_b3);
    cudaGetSymbolAddress((void**)&QKV, g_QKV);
    cudaGetSymbolAddress((void**)&Vth, g_Vth);
    cudaGetSymbolAddress((void**)&Sch, g_Sch);
    cudaGetSymbolAddress((void**)&Ph,  g_Ph);

    cudaFuncSetAttribute(gemm1_mma_kernel,
                         cudaFuncAttributeMaxDynamicSharedMemorySize, SMEM_BYTES);

    // Convert inputs to fp16 + pack bias
    {
        int n4 = ROWS * HID / 4;
        cvt_kernel<<<(n4 + 255) / 256, 256>>>(X, Xh, n4);
        int w4 = HID * HID / 4;
        cvt_kernel<<<(w4 + 255) / 256, 256>>>(Wq, Wh, w4);
        cvt_kernel<<<(w4 + 255) / 256, 256>>>(Wk, Wh + (size_t)HID * HID, w4);
        cvt_kernel<<<(w4 + 255) / 256, 256>>>(Wv, Wh + (size_t)2 * HID * HID, w4);
        pack_bias_kernel<<<3, HID>>>(bq, bk, bv, b3);
    }

    dim3 blk(512);

    // Fused QKV projection: [8192, 3072] = X @ [Wq|Wk|Wv]^T + b3 (fp16 out)
    {
        dim3 g(3 * HID / 256, ROWS / 128, 1);
        gemm1_mma_kernel<<<g, blk, SMEM_BYTES>>>(Xh, Wh, b3,
                                                 nullptr, QKV,
                                                 HID, HID, HID, 3 * HID, 1.0f,
                                                 0, 0, 0);
    }

    // V slice -> Vt [b][h][s]
    {
        dim3 gt(HID / 32, SEQ / 32, NB);
        transpose_h_kernel<<<gt, 256>>>(QKV, Vth);
    }

    // scores[b] = Q[b] @ K[b]^T / 32  (fp16 out)
    {
        dim3 g(SEQ / 256, SEQ / 128, NB);
        gemm1_mma_kernel<<<g, blk, SMEM_BYTES>>>(QKV, QKV + HID, nullptr,
                                                 nullptr, Sch,
                                                 HID, 3 * HID, 3 * HID, SEQ, 0.03125f,
                                                 (size_t)SEQ * 3 * HID,
                                                 (size_t)SEQ * 3 * HID,
                                                 (size_t)SEQ * SEQ);
    }

    // softmax -> fp16 P
    softmax_h_kernel<<<NB * SEQ, 256>>>(Sch, Ph);

    // out[b] = P[b] @ Vt[b]^T
    {
        dim3 g(HID / 256, SEQ / 128, NB);
        gemm1_mma_kernel<<<g, blk, SMEM_BYTES>>>(Ph, Vth, nullptr,
                                                 out, nullptr,
                                                 SEQ, SEQ, SEQ, HID, 1.0f,
                                                 (size_t)SEQ * SEQ,
                                                 (size_t)SEQ * HID,
                                                 (size_t)SEQ * HID);
    }
}

// round 17
// speedup vs baseline: 1.0199x; 1.0199x over previous
#include <cuda_runtime.h>
#include <cuda_fp16.h>
#include <cstdint>

// Problem constants
static constexpr int HID  = 1024;
static constexpr int NB   = 4;
static constexpr int SEQ  = 2048;
static constexpr int ROWS = NB * SEQ; // 8192

// ---------------------------------------------------------------------------
// Scratch (device globals; allocation-free rule). Everything fp16 except the
// final output. QKV is one fused [8192, 3072] buffer (Q | K | V columns).
// ---------------------------------------------------------------------------
__device__ __half g_Xh [(size_t)ROWS * HID];
__device__ __half g_Wh [(size_t)3 * HID * HID];   // stacked Wq|Wk|Wv, [3072,1024]
__device__ float  g_b3 [3 * HID];                 // packed bq|bk|bv
__device__ __half g_QKV[(size_t)ROWS * 3 * HID];  // [8192, 3072]
__device__ __half g_Vth[(size_t)ROWS * HID];      // [b][h][s]
__device__ __half g_Sch[(size_t)NB * SEQ * SEQ];  // scores fp16 (pre-softmax)
__device__ __half g_Ph [(size_t)NB * SEQ * SEQ];  // softmax(P) fp16

// ---------------------------------------------------------------------------
// PTX helpers
// ---------------------------------------------------------------------------
__device__ __forceinline__ uint32_t smem_u32(const void* p) {
    uint32_t a;
    asm("{ .reg .u64 t; cvta.to.shared.u64 t, %1; cvt.u32.u64 %0, t; }"
        : "=r"(a) : "l"(p));
    return a;
}
__device__ __forceinline__ void cp_async16(uint32_t dst, const void* src) {
    asm volatile("cp.async.cg.shared.global [%0], [%1], 16;"
                 :: "r"(dst), "l"(src) : "memory");
}
#define CP_COMMIT()  asm volatile("cp.async.commit_group;" ::: "memory")
#define CP_WAIT(n)   asm volatile("cp.async.wait_group %0;" :: "n"(n) : "memory")

__device__ __forceinline__ void ldm_x4(uint32_t& r0, uint32_t& r1,
                                       uint32_t& r2, uint32_t& r3, uint32_t addr) {
    asm volatile("ldmatrix.sync.aligned.m8n8.x4.shared.b16 {%0,%1,%2,%3}, [%4];"
                 : "=r"(r0), "=r"(r1), "=r"(r2), "=r"(r3) : "r"(addr));
}
__device__ __forceinline__ void mma_f16(float& d0, float& d1, float& d2, float& d3,
                                        uint32_t a0, uint32_t a1, uint32_t a2, uint32_t a3,
                                        uint32_t b0, uint32_t b1) {
    asm volatile(
        "mma.sync.aligned.m16n8k16.row.col.f32.f16.f16.f32 "
        "{%0,%1,%2,%3}, {%4,%5,%6,%7}, {%8,%9}, {%0,%1,%2,%3};"
        : "+f"(d0), "+f"(d1), "+f"(d2), "+f"(d3)
        : "r"(a0), "r"(a1), "r"(a2), "r"(a3), "r"(b0), "r"(b1));
}

// ---------------------------------------------------------------------------
// Tile config: BM=128, BN=256, BK=64, 4 stages, 512 threads (16 warps, 4x4).
// Rows padded to 144B: conflict-free ldmatrix. Per stage: A[128x64]+B[256x64].
// ---------------------------------------------------------------------------
static constexpr int RS        = 144;
static constexpr int B_OFF     = 128 * RS;            // 18432
static constexpr int STG_BYTES = B_OFF + 256 * RS;    // 55296
static constexpr int SMEM_BYTES = 4 * STG_BYTES;      // 221184

__device__ __forceinline__ void stage_load(
    const __half* __restrict__ Ah, const __half* __restrict__ Bh,
    int lda, int ldb, int k0, uint32_t sb, int tid)
{
#pragma unroll
    for (int i = 0; i < 2; i++) {
        const int v = tid + (i << 9);
        const int r = v >> 3, c = v & 7;
        cp_async16(sb + (uint32_t)(r * RS + (c << 4)),
                   Ah + (size_t)r * lda + k0 + (c << 3));
    }
#pragma unroll
    for (int i = 0; i < 4; i++) {
        const int v = tid + (i << 9);
        const int r = v >> 3, c = v & 7;
        cp_async16(sb + (uint32_t)(B_OFF + r * RS + (c << 4)),
                   Bh + (size_t)r * ldb + k0 + (c << 3));
    }
}

// ---------------------------------------------------------------------------
// Single-pass fp16 GEMM NT: C = alpha * A·B^T + bias
// A: [M,K] fp16 lead-dim lda; B: [N,K] fp16 lead-dim ldb.
// C!=null -> fp32 out (ldc); Ch!=null -> fp16 out (ldc). blockIdx.z batches.
// Register-level fragment double buffering hides LDSM latency under MMAs.
// ---------------------------------------------------------------------------
__global__ void __launch_bounds__(512, 1)
gemm1_mma_kernel(const __half* __restrict__ Ah, const __half* __restrict__ Bh,
                 const float* __restrict__ bias,
                 float* __restrict__ C, __half* __restrict__ Ch,
                 int K, int lda, int ldb, int ldc, float alpha,
                 size_t sA, size_t sB, size_t sC)
{
    extern __shared__ char smem[];
    const uint32_t sbase = smem_u32(smem);
    const int tid = threadIdx.x;
    const int wid = tid >> 5;
    const int lid = tid & 31;
    const int wm  = wid >> 2;   // 0..3 : 32-row slab
    const int wn  = wid & 3;    // 0..3 : 64-col slab

    Ah += (size_t)blockIdx.z * sA + (size_t)blockIdx.y * 128 * lda;
    Bh += (size_t)blockIdx.z * sB + (size_t)blockIdx.x * 256 * ldb;
    const size_t zC = (size_t)blockIdx.z * sC;

    float acc[2][8][4];
#pragma unroll
    for (int mi = 0; mi < 2; mi++)
#pragma unroll
        for (int ni = 0; ni < 8; ni++)
#pragma unroll
            for (int r = 0; r < 4; r++) acc[mi][ni][r] = 0.0f;

    const int nch = K >> 6;

    stage_load(Ah, Bh, lda, ldb, 0, sbase, tid);
    CP_COMMIT();
    stage_load(Ah, Bh, lda, ldb, 64, sbase + STG_BYTES, tid);
    CP_COMMIT();
    stage_load(Ah, Bh, lda, ldb, 128, sbase + 2 * STG_BYTES, tid);
    CP_COMMIT();

    const int a_row = wm * 32 + (((lid >> 3) & 1) << 3) + (lid & 7); // + mi*16
    const int a_chs = (lid >> 4) & 1;                                // + ks*2
    const int b_row = wn * 64 + (((lid >> 4) & 1) << 3) + (lid & 7); // + pr*16
    const int b_chs = (lid >> 3) & 1;                                // + ks*2

    // Fragment double buffers
    uint32_t ahf[2][2][4]; // [buf][mi][reg]
    uint32_t bhf[2][4];    // [buf][reg]

    // stages 0 and 1 guaranteed complete (3 groups committed, wait(1))
    CP_WAIT(1);
    __syncthreads();

    // Preload first fragments of chunk 0
    {
        const uint32_t tb = sbase;
        const uint32_t acol = (uint32_t)(a_chs << 4);
        const uint32_t bcol = (uint32_t)(b_chs << 4);
#pragma unroll
        for (int mi = 0; mi < 2; mi++)
            ldm_x4(ahf[0][mi][0], ahf[0][mi][1], ahf[0][mi][2], ahf[0][mi][3],
                   tb + (uint32_t)((a_row + mi * 16) * RS) + acol);
        ldm_x4(bhf[0][0], bhf[0][1], bhf[0][2], bhf[0][3],
               tb + (uint32_t)(B_OFF + b_row * RS) + bcol);
    }

    for (int c = 0; c < nch; c++) {
        // Refill slot freed by chunk c-1 (protected by prior __syncthreads)
        if (c + 3 < nch)
            stage_load(Ah, Bh, lda, ldb, (c + 3) << 6,
                       sbase + (uint32_t)(((c + 3) & 3) * STG_BYTES), tid);
        CP_COMMIT();   // always commit: uniform group count keeps CP_WAIT exact

        const uint32_t tb  = sbase + (uint32_t)((c & 3) * STG_BYTES);
        const uint32_t tbn = sbase + (uint32_t)(((c + 1) & 3) * STG_BYTES);

#pragma unroll
        for (int ks = 0; ks < 4; ks++) {
            const int abuf = ks & 1;
#pragma unroll
            for (int pr = 0; pr < 4; pr++) {
                const int bbuf = pr & 1;
                // Prefetch the next fragment set while current MMAs issue
                if (pr < 3) {
                    const uint32_t bcol = (uint32_t)(((ks << 1) + b_chs) << 4);
                    ldm_x4(bhf[!bbuf][0], bhf[!bbuf][1], bhf[!bbuf][2], bhf[!bbuf][3],
                           tb + (uint32_t)(B_OFF + (b_row + (pr + 1) * 16) * RS) + bcol);
                } else if (ks < 3) {
                    const uint32_t acol = (uint32_t)((((ks + 1) << 1) + a_chs) << 4);
                    const uint32_t bcol = (uint32_t)((((ks + 1) << 1) + b_chs) << 4);
#pragma unroll
                    for (int mi = 0; mi < 2; mi++)
                        ldm_x4(ahf[!abuf][mi][0], ahf[!abuf][mi][1],
                               ahf[!abuf][mi][2], ahf[!abuf][mi][3],
                               tb + (uint32_t)((a_row + mi * 16) * RS) + acol);
                    ldm_x4(bhf[0][0], bhf[0][1], bhf[0][2], bhf[0][3],
                           tb + (uint32_t)(B_OFF + b_row * RS) + bcol);
                } else if (c + 1 < nch) {
                    // Chunk tail: stage c+1 is resident (CP_WAIT(1) invariant)
                    const uint32_t acol = (uint32_t)(a_chs << 4);
                    const uint32_t bcol = (uint32_t)(b_chs << 4);
#pragma unroll
                    for (int mi = 0; mi < 2; mi++)
                        ldm_x4(ahf[0][mi][0], ahf[0][mi][1],
                               ahf[0][mi][2], ahf[0][mi][3],
                               tbn + (uint32_t)((a_row + mi * 16) * RS) + acol);
                    ldm_x4(bhf[0][0], bhf[0][1], bhf[0][2], bhf[0][3],
                           tbn + (uint32_t)(B_OFF + b_row * RS) + bcol);
                }
                // 4 MMAs on the current fragments
#pragma unroll
                for (int mi = 0; mi < 2; mi++)
#pragma unroll
                    for (int q = 0; q < 2; q++) {
                        const int of = q << 1;
                        float* d = acc[mi][pr * 2 + q];
                        mma_f16(d[0], d[1], d[2], d[3],
                                ahf[abuf][mi][0], ahf[abuf][mi][1],
                                ahf[abuf][mi][2], ahf[abuf][mi][3],
                                bhf[bbuf][of], bhf[bbuf][of + 1]);
                    }
            }
        }

        CP_WAIT(1);        // stages c+1 (already) and c+2 complete after this
        __syncthreads();   // all warps done reading chunk c -> safe to refill
    }

    // Epilogue
    const int t4 = lid >> 2;
    const int t2 = (lid & 3) << 1;
#pragma unroll
    for (int ni = 0; ni < 8; ni++) {
        const int gcol = blockIdx.x * 256 + wn * 64 + ni * 8 + t2;
        float bi0 = 0.0f, bi1 = 0.0f;
        if (bias) { bi0 = bias[gcol]; bi1 = bias[gcol + 1]; }
#pragma unroll
        for (int mi = 0; mi < 2; mi++) {
            const int grow = blockIdx.y * 128 + wm * 32 + mi * 16 + t4;
            const float* d = acc[mi][ni];
            float v00 = fmaf(alpha, d[0], bi0);
            float v01 = fmaf(alpha, d[1], bi1);
            float v10 = fmaf(alpha, d[2], bi0);
            float v11 = fmaf(alpha, d[3], bi1);
            const size_t o0 = zC + (size_t)grow * ldc + gcol;
            const size_t o1 = o0 + (size_t)8 * ldc;
            if (C) {
                *reinterpret_cast<float2*>(C + o0) = make_float2(v00, v01);
                *reinterpret_cast<float2*>(C + o1) = make_float2(v10, v11);
            }
            if (Ch) {
                *reinterpret_cast<__half2*>(Ch + o0) =
                    __halves2half2(__float2half(v00), __float2half(v01));
                *reinterpret_cast<__half2*>(Ch + o1) =
                    __halves2half2(__float2half(v10), __float2half(v11));
            }
        }
    }
}

// ---------------------------------------------------------------------------
// fp32 -> fp16 convert, vectorized by 4
// ---------------------------------------------------------------------------
__global__ void __launch_bounds__(256)
cvt_kernel(const float* __restrict__ x, __half* __restrict__ hi, int n4)
{
    int i = blockIdx.x * 256 + threadIdx.x;
    if (i >= n4) return;
    float4 v = reinterpret_cast<const float4*>(x)[i];
    reinterpret_cast<__half2*>(hi)[2 * i] =
        __halves2half2(__float2half(v.x), __float2half(v.y));
    reinterpret_cast<__half2*>(hi)[2 * i + 1] =
        __halves2half2(__float2half(v.z), __float2half(v.w));
}

// Pack bq|bk|bv into one 3072 vector
__global__ void pack_bias_kernel(const float* __restrict__ bq,
                                 const float* __restrict__ bk,
                                 const float* __restrict__ bv,
                                 float* __restrict__ b3)
{
    const int tid = threadIdx.x;
    const float* src = (blockIdx.x == 0) ? bq : (blockIdx.x == 1) ? bk : bv;
    b3[blockIdx.x * HID + tid] = src[tid];
}

// ---------------------------------------------------------------------------
// V slice of QKV [8192, 3072] (cols 2048..3071) fp16 -> Vt [b][h][s] fp16
// ---------------------------------------------------------------------------
__global__ void __launch_bounds__(256)
transpose_h_kernel(const __half* __restrict__ QKV, __half* __restrict__ Th)
{
    __shared__ __half tile[32][34];
    const int b = blockIdx.z;
    const int h0 = blockIdx.x * 32, s0 = blockIdx.y * 32;
    const int tx = threadIdx.x & 31, ty = threadIdx.x >> 5; // 32 x 8
    const __half* Vb = QKV + (size_t)b * SEQ * (3 * HID) + 2 * HID;
#pragma unroll
    for (int j = 0; j < 32; j += 8)
        tile[ty + j][tx] = Vb[(size_t)(s0 + ty + j) * (3 * HID) + h0 + tx];
    __syncthreads();
    __half* Thb = Th + (size_t)b * HID * SEQ;
#pragma unroll
    for (int j = 0; j < 32; j += 8)
        Thb[(size_t)(h0 + ty + j) * SEQ + s0 + tx] = tile[tx][ty + j];
}

// ---------------------------------------------------------------------------
// Row softmax (2048 cols), fp16 in -> fp16 out
// ---------------------------------------------------------------------------
__global__ void __launch_bounds__(256)
softmax_h_kernel(const __half* __restrict__ Sc, __half* __restrict__ Ph)
{
    __shared__ float red[256];
    const int tid = threadIdx.x;
    const __half2* row = reinterpret_cast<const __half2*>(Sc + (size_t)blockIdx.x * SEQ);

    __half2 h[4];
#pragma unroll
    for (int j = 0; j < 4; j++) h[j] = row[4 * tid + j];
    float p[8];
#pragma unroll
    for (int j = 0; j < 4; j++) {
        float2 f = __half22float2(h[j]);
        p[2 * j] = f.x; p[2 * j + 1] = f.y;
    }

    float m = p[0];
#pragma unroll
    for (int j = 1; j < 8; j++) m = fmaxf(m, p[j]);
    red[tid] = m;
    __syncthreads();
#pragma unroll
    for (int s = 128; s > 0; s >>= 1) {
        if (tid < s) red[tid] = fmaxf(red[tid], red[tid + s]);
        __syncthreads();
    }
    m = red[0];
    __syncthreads();

    float sum = 0.0f;
#pragma unroll
    for (int j = 0; j < 8; j++) { p[j] = __expf(p[j] - m); sum += p[j]; }
    red[tid] = sum;
    __syncthreads();
#pragma unroll
    for (int s = 128; s > 0; s >>= 1) {
        if (tid < s) red[tid] += red[tid + s];
        __syncthreads();
    }
    const float inv = 1.0f / red[0];

    __half2* H = reinterpret_cast<__half2*>(Ph + (size_t)blockIdx.x * SEQ);
#pragma unroll
    for (int j = 0; j < 4; j++)
        H[4 * tid + j] = __halves2half2(__float2half(p[2 * j] * inv),
                                        __float2half(p[2 * j + 1] * inv));
}

// ---------------------------------------------------------------------------
// Launch
// ---------------------------------------------------------------------------
extern "C" void kernel_launch(void* const* d_in, const int* in_sizes, int n_in,
                              void* d_out, int out_size)
{
    const float* X  = (const float*)d_in[0];
    const float* Wq = (const float*)d_in[1];
    const float* bq = (const float*)d_in[2];
    const float* Wk = (const float*)d_in[3];
    const float* bk = (const float*)d_in[4];
    const float* Wv = (const float*)d_in[5];
    const float* bv = (const float*)d_in[6];
    float* out = (float*)d_out;

    __half *Xh, *Wh, *QKV, *Vth, *Sch, *Ph;
    float *b3;
    cudaGetSymbolAddress((void**)&Xh,  g_Xh);
    cudaGetSymbolAddress((void**)&Wh,  g_Wh);
    cudaGetSymbolAddress((void**)&b3,  g_b3);
    cudaGetSymbolAddress((void**)&QKV, g_QKV);
    cudaGetSymbolAddress((void**)&Vth, g_Vth);
    cudaGetSymbolAddress((void**)&Sch, g_Sch);
    cudaGetSymbolAddress((void**)&Ph,  g_Ph);

    cudaFuncSetAttribute(gemm1_mma_kernel,
                         cudaFuncAttributeMaxDynamicSharedMemorySize, SMEM_BYTES);

    // Convert inputs to fp16 + pack bias
    {
        int n4 = ROWS * HID / 4;
        cvt_kernel<<<(n4 + 255) / 256, 256>>>(X, Xh, n4);
        int w4 = HID * HID / 4;
        cvt_kernel<<<(w4 + 255) / 256, 256>>>(Wq, Wh, w4);
        cvt_kernel<<<(w4 + 255) / 256, 256>>>(Wk, Wh + (size_t)HID * HID, w4);
        cvt_kernel<<<(w4 + 255) / 256, 256>>>(Wv, Wh + (size_t)2 * HID * HID, w4);
        pack_bias_kernel<<<3, HID>>>(bq, bk, bv, b3);
    }

    dim3 blk(512);

    // Fused QKV projection: [8192, 3072] = X @ [Wq|Wk|Wv]^T + b3 (fp16 out)
    {
        dim3 g(3 * HID / 256, ROWS / 128, 1);
        gemm1_mma_kernel<<<g, blk, SMEM_BYTES>>>(Xh, Wh, b3,
                                                 nullptr, QKV,
                                                 HID, HID, HID, 3 * HID, 1.0f,
                                                 0, 0, 0);
    }

    // V slice -> Vt [b][h][s]
    {
        dim3 gt(HID / 32, SEQ / 32, NB);
        transpose_h_kernel<<<gt, 256>>>(QKV, Vth);
    }

    // scores[b] = Q[b] @ K[b]^T / 32  (fp16 out)
    {
        dim3 g(SEQ / 256, SEQ / 128, NB);
        gemm1_mma_kernel<<<g, blk, SMEM_BYTES>>>(QKV, QKV + HID, nullptr,
                                                 nullptr, Sch,
                                                 HID, 3 * HID, 3 * HID, SEQ, 0.03125f,
                                                 (size_t)SEQ * 3 * HID,
                                                 (size_t)SEQ * 3 * HID,
                                                 (size_t)SEQ * SEQ);
    }

    // softmax -> fp16 P
    softmax_h_kernel<<<NB * SEQ, 256>>>(Sch, Ph);

    // out[b] = P[b] @ Vt[b]^T
    {
        dim3 g(HID / 256, SEQ / 128, NB);
        gemm1_mma_kernel<<<g, blk, SMEM_BYTES>>>(Ph, Vth, nullptr,
                                                 out, nullptr,
                                                 SEQ, SEQ, SEQ, HID, 1.0f,
                                                 (size_t)SEQ * SEQ,
                                                 (size_t)SEQ * HID,
                                                 (size_t)SEQ * HID);
    }
}